// round 6
// baseline (speedup 1.0000x reference)
#include <cuda_runtime.h>
#include <cstdint>

#define NB     1024
#define NK     5
#define NV     32000
#define ND     128
#define NSPLIT 50

// ---------------- scratch (device globals; no allocation allowed) ----------
__device__ uint32_t g_Vt[ND * (NV / 2)];        // V^T bf16x2 [d][v-word]   8.2 MB
__device__ uint32_t g_Ub[NV * (ND / 2)];        // U   bf16x2 [v][d-word]   8.2 MB
__device__ float    g_part[NSPLIT * NB * ND];   // split-K partials        26.2 MB
__device__ uint32_t g_vi_bf16[NB * (ND / 2)];   // packed vi_embed         256 KB
__device__ float    g_pos[NB];
__device__ float    g_negacc[NB * NK];
__device__ int      g_ctr;

// ---------------- helpers ----------------------------------------------------
static __device__ __forceinline__ uint32_t pack_bf16x2(float lo, float hi) {
    uint32_t r;
    asm("cvt.rn.bf16x2.f32 %0, %1, %2;" : "=r"(r) : "f"(hi), "f"(lo));
    return r;
}

static __device__ __forceinline__ void mma_bf16(
    float c[4], uint32_t a0, uint32_t a1, uint32_t a2, uint32_t a3,
    uint32_t b0, uint32_t b1)
{
    asm volatile(
        "mma.sync.aligned.m16n8k16.row.col.f32.bf16.bf16.f32 "
        "{%0,%1,%2,%3}, {%4,%5,%6,%7}, {%8,%9}, {%0,%1,%2,%3};"
        : "+f"(c[0]), "+f"(c[1]), "+f"(c[2]), "+f"(c[3])
        : "r"(a0), "r"(a1), "r"(a2), "r"(a3), "r"(b0), "r"(b1));
}

static __device__ __forceinline__ float logsig(float x) {
    float z = -fabsf(x);
    float l = log1pf(__expf(z));
    return (x >= 0.0f) ? -l : (x - l);
}

// ---------------- kernel P: prep (V^T->bf16, U->bf16, zero accumulators) ----
// blocks [0,4000): V transpose tiles 32v x 32d; blocks [4000,5000): U convert.
__global__ void __launch_bounds__(256)
prep_kernel(const float* __restrict__ Vm, const float* __restrict__ U)
{
    const int blk = blockIdx.x;
    const int tid = threadIdx.x;

    if (blk < 4000) {
        __shared__ float sm[32][33];
        const int v0 = (blk % 1000) * 32;
        const int d0 = (blk / 1000) * 32;
        #pragma unroll
        for (int p = 0; p < 4; p++) {
            int i = (tid >> 5) + p * 8;
            int j = tid & 31;
            sm[i][j] = Vm[(size_t)(v0 + i) * ND + d0 + j];
        }
        __syncthreads();
        #pragma unroll
        for (int o = 0; o < 2; o++) {
            int row = (tid >> 4) + o * 16;   // d within tile
            int w   = tid & 15;              // v-word within tile
            uint32_t val = pack_bf16x2(sm[2 * w][row], sm[2 * w + 1][row]);
            g_Vt[(size_t)(d0 + row) * (NV / 2) + (v0 >> 1) + w] = val;
        }
    } else {
        int i0 = (blk - 4000) * 256 + tid;
        #pragma unroll
        for (int p = 0; p < 4; p++) {
            int i = i0 + p * 256000;
            float4 f = ((const float4*)U)[i];
            uint2 o;
            o.x = pack_bf16x2(f.x, f.y);
            o.y = pack_bf16x2(f.z, f.w);
            ((uint2*)g_Ub)[i] = o;
        }
        if (blk == 4000) {
            for (int i = tid; i < NB; i += 256)      g_pos[i] = 0.0f;
            for (int i = tid; i < NB * NK; i += 256) g_negacc[i] = 0.0f;
        }
    }
}

// ---------------- kernel 1: partials of vi @ V  (bf16, split-K, pipelined) --
// grid (8 m-tiles, 50 k-splits); 10 chunks of k=64; double-buffered smem;
// plain STG partial output (no atomics).
#define G1S 36
static constexpr int SMEM1 = 2 * 2 * 128 * G1S * 4;   // 73728 B (A+B, 2 bufs)

__global__ void __launch_bounds__(256, 1)
gemm1_kernel(const float* __restrict__ vi)
{
    extern __shared__ uint32_t sm1[];
    // buffer p: A at p*(2*128*G1S), B at that + 128*G1S
    const int tid  = threadIdx.x;
    const int wid  = tid >> 5;
    const int lane = tid & 31;
    const int g    = lane >> 2;
    const int tig  = lane & 3;
    const int m0   = blockIdx.x * 128;
    const int wrow = wid * 16;
    const int split = blockIdx.y;
    const size_t kbase = (size_t)split * 640;

    float acc[16][4];
    #pragma unroll
    for (int nt = 0; nt < 16; nt++)
        #pragma unroll
        for (int j = 0; j < 4; j++) acc[nt][j] = 0.0f;

    float4 ra[8];
    uint4  rbv[4];
    const int ar = tid >> 4, ac4 = tid & 15;   // A: 16 float4/row
    const int brr = tid >> 3, bw4 = tid & 7;   // B: 8 uint4/row (32 words)

    #define G1_LDG(IT)                                                            \
        do {                                                                      \
            size_t k0 = kbase + (size_t)(IT) * 64;                                \
            _Pragma("unroll")                                                     \
            for (int t = 0; t < 8; t++)                                           \
                ra[t] = *(const float4*)(vi + (size_t)(m0 + ar + t * 16) * NV + k0 + ac4 * 4); \
            _Pragma("unroll")                                                     \
            for (int t = 0; t < 4; t++)                                           \
                rbv[t] = *(const uint4*)(g_Vt + (size_t)(brr + t * 32) * (NV / 2) + (k0 >> 1) + bw4 * 4); \
        } while (0)

    #define G1_STS(P)                                                             \
        do {                                                                      \
            uint32_t* Aw = sm1 + (P) * (2 * 128 * G1S);                           \
            uint32_t* Bw = Aw + 128 * G1S;                                        \
            _Pragma("unroll")                                                     \
            for (int t = 0; t < 8; t++) {                                         \
                uint2 p;                                                          \
                p.x = pack_bf16x2(ra[t].x, ra[t].y);                              \
                p.y = pack_bf16x2(ra[t].z, ra[t].w);                              \
                *(uint2*)(Aw + (ar + t * 16) * G1S + ac4 * 2) = p;                \
            }                                                                     \
            _Pragma("unroll")                                                     \
            for (int t = 0; t < 4; t++)                                           \
                *(uint4*)(Bw + (brr + t * 32) * G1S + bw4 * 4) = rbv[t];          \
        } while (0)

    G1_LDG(0);
    G1_STS(0);
    __syncthreads();

    for (int it = 0; it < 10; it++) {
        if (it + 1 < 10) G1_LDG(it + 1);

        const uint32_t* Aw = sm1 + (it & 1) * (2 * 128 * G1S);
        const uint32_t* Bw = Aw + 128 * G1S;

        #pragma unroll
        for (int ks = 0; ks < 4; ks++) {
            const int kw = ks * 8;
            uint32_t a0 = Aw[(wrow + g)     * G1S + kw + tig];
            uint32_t a1 = Aw[(wrow + g + 8) * G1S + kw + tig];
            uint32_t a2 = Aw[(wrow + g)     * G1S + kw + tig + 4];
            uint32_t a3 = Aw[(wrow + g + 8) * G1S + kw + tig + 4];
            #pragma unroll
            for (int nt = 0; nt < 16; nt++) {
                uint32_t b0 = Bw[(nt * 8 + g) * G1S + kw + tig];
                uint32_t b1 = Bw[(nt * 8 + g) * G1S + kw + tig + 4];
                mma_bf16(acc[nt], a0, a1, a2, a3, b0, b1);
            }
        }

        if (it + 1 < 10) {
            G1_STS(1 - (it & 1));
            __syncthreads();
        }
    }

    // epilogue: plain stores of split-K partials (no atomics)
    float* dst0 = g_part + ((size_t)split * NB + (m0 + wrow + g)) * ND + 2 * tig;
    float* dst1 = dst0 + 8 * ND;
    #pragma unroll
    for (int nt = 0; nt < 16; nt++) {
        float2 v0 = make_float2(acc[nt][0], acc[nt][1]);
        float2 v1 = make_float2(acc[nt][2], acc[nt][3]);
        *(float2*)(dst0 + nt * 8) = v0;
        *(float2*)(dst1 + nt * 8) = v1;
    }
}

// ---------------- kernel R: reduce partials -> packed bf16 vi_embed ---------
__global__ void __launch_bounds__(256)
reduce_kernel()
{
    int e4 = blockIdx.x * 256 + threadIdx.x;   // float4 index, 32768 total
    float4 a = make_float4(0.f, 0.f, 0.f, 0.f);
    #pragma unroll 10
    for (int s = 0; s < NSPLIT; s++) {
        float4 f = *(const float4*)(g_part + (size_t)s * (NB * ND) + (size_t)e4 * 4);
        a.x += f.x; a.y += f.y; a.z += f.z; a.w += f.w;
    }
    uint2 o;
    o.x = pack_bf16x2(a.x, a.y);
    o.y = pack_bf16x2(a.z, a.w);
    ((uint2*)g_vi_bf16)[e4] = o;
}

// ---------------- kernel 2: w = vi_embed @ U^T + fused streams + finalize ---
#define S2W 68
static constexpr int SMEM2 = 2 * 128 * S2W * 4;   // 69632 B

__global__ void __launch_bounds__(256, 2)
gemm2_kernel(const float* __restrict__ vo, const float* __restrict__ neg,
             float* __restrict__ out)
{
    extern __shared__ uint32_t sm2[];
    uint32_t* As = sm2;              // [128][S2W] bf16x2: vi_embed (row=b)
    uint32_t* Bs = sm2 + 128 * S2W;  // [128][S2W] bf16x2: U        (row=v)

    const int tid  = threadIdx.x;
    const int wid  = tid >> 5;
    const int lane = tid & 31;
    const int g    = lane >> 2;
    const int tig  = lane & 3;
    const int m0   = blockIdx.x * 128;
    const int v0   = blockIdx.y * 128;
    const int wrow = wid * 16;

    // tile loads: already bf16x2-packed in gmem
    #pragma unroll
    for (int t = 0; t < 16; t++) {
        int r = wid + t * 8;
        uint2 w2 = *(const uint2*)(g_vi_bf16 + (size_t)(m0 + r) * (ND / 2) + lane * 2);
        *(uint2*)(As + r * S2W + lane * 2) = w2;
    }
    #pragma unroll
    for (int t = 0; t < 16; t++) {
        int r = wid + t * 8;
        uint2 w2 = *(const uint2*)(g_Ub + (size_t)(v0 + r) * (ND / 2) + lane * 2);
        *(uint2*)(Bs + r * S2W + lane * 2) = w2;
    }
    __syncthreads();

    // cache A fragments for all 8 k-steps
    uint32_t af[8][4];
    #pragma unroll
    for (int ks = 0; ks < 8; ks++) {
        const int kw = ks * 8;
        af[ks][0] = As[(wrow + g)     * S2W + kw + tig];
        af[ks][1] = As[(wrow + g + 8) * S2W + kw + tig];
        af[ks][2] = As[(wrow + g)     * S2W + kw + tig + 4];
        af[ks][3] = As[(wrow + g + 8) * S2W + kw + tig + 4];
    }

    const int r0 = m0 + wrow + g;
    const int r1 = r0 + 8;
    const int cb = v0 + 2 * tig;
    const float* vp0 = vo + (size_t)r0 * NV + cb;
    const float* vp1 = vo + (size_t)r1 * NV + cb;
    const float* np0 = neg + (size_t)r0 * NK * NV + cb;
    const float* np1 = neg + (size_t)r1 * NK * NV + cb;

    float2 cv0 = *(const float2*)(vp0);
    float2 cv1 = *(const float2*)(vp1);
    float2 cn0[NK], cn1[NK];
    #pragma unroll
    for (int k = 0; k < NK; k++) {
        cn0[k] = *(const float2*)(np0 + (size_t)k * NV);
        cn1[k] = *(const float2*)(np1 + (size_t)k * NV);
    }

    float sp0 = 0.0f, sp1 = 0.0f;
    float sn0[NK], sn1[NK];
    #pragma unroll
    for (int k = 0; k < NK; k++) { sn0[k] = 0.0f; sn1[k] = 0.0f; }

    #pragma unroll
    for (int nt = 0; nt < 16; nt++) {
        float2 xv0, xv1, xn0[NK], xn1[NK];
        if (nt < 15) {
            const int off = (nt + 1) * 8;
            xv0 = *(const float2*)(vp0 + off);
            xv1 = *(const float2*)(vp1 + off);
            #pragma unroll
            for (int k = 0; k < NK; k++) {
                xn0[k] = *(const float2*)(np0 + (size_t)k * NV + off);
                xn1[k] = *(const float2*)(np1 + (size_t)k * NV + off);
            }
        }

        float a4[4] = {0.0f, 0.0f, 0.0f, 0.0f};
        #pragma unroll
        for (int ks = 0; ks < 8; ks++) {
            uint32_t b0 = Bs[(nt * 8 + g) * S2W + ks * 8 + tig];
            uint32_t b1 = Bs[(nt * 8 + g) * S2W + ks * 8 + tig + 4];
            mma_bf16(a4, af[ks][0], af[ks][1], af[ks][2], af[ks][3], b0, b1);
        }

        sp0 += cv0.x * a4[0] + cv0.y * a4[1];
        sp1 += cv1.x * a4[2] + cv1.y * a4[3];
        #pragma unroll
        for (int k = 0; k < NK; k++) {
            sn0[k] += cn0[k].x * a4[0] + cn0[k].y * a4[1];
            sn1[k] += cn1[k].x * a4[2] + cn1[k].y * a4[3];
        }

        if (nt < 15) {
            cv0 = xv0; cv1 = xv1;
            #pragma unroll
            for (int k = 0; k < NK; k++) { cn0[k] = xn0[k]; cn1[k] = xn1[k]; }
        }
    }

    #pragma unroll
    for (int o = 1; o <= 2; o <<= 1) {
        sp0 += __shfl_xor_sync(0xFFFFFFFFu, sp0, o);
        sp1 += __shfl_xor_sync(0xFFFFFFFFu, sp1, o);
        #pragma unroll
        for (int k = 0; k < NK; k++) {
            sn0[k] += __shfl_xor_sync(0xFFFFFFFFu, sn0[k], o);
            sn1[k] += __shfl_xor_sync(0xFFFFFFFFu, sn1[k], o);
        }
    }
    if (tig == 0) {
        atomicAdd(&g_pos[r0], sp0);
        atomicAdd(&g_pos[r1], sp1);
        #pragma unroll
        for (int k = 0; k < NK; k++) {
            atomicAdd(&g_negacc[r0 * NK + k], sn0[k]);
            atomicAdd(&g_negacc[r1 * NK + k], sn1[k]);
        }
    }

    // ---- last-CTA finalize ----
    __syncthreads();
    __shared__ int is_last;
    if (tid == 0) {
        __threadfence();
        int old = atomicAdd(&g_ctr, 1);
        is_last = (old == (int)(gridDim.x * gridDim.y) - 1) ? 1 : 0;
    }
    __syncthreads();
    if (is_last) {
        __threadfence();
        float v = 0.0f;
        #pragma unroll
        for (int j = 0; j < 4; j++) {
            int b = tid * 4 + j;
            float l = logsig(__ldcg(&g_pos[b]));
            #pragma unroll
            for (int k = 0; k < NK; k++)
                l += logsig(-__ldcg(&g_negacc[b * NK + k]));
            v += -l;
        }
        #pragma unroll
        for (int o = 16; o > 0; o >>= 1) v += __shfl_xor_sync(0xFFFFFFFFu, v, o);
        __shared__ float red[8];
        if (lane == 0) red[wid] = v;
        __syncthreads();
        if (tid == 0) {
            float s = 0.0f;
            #pragma unroll
            for (int i = 0; i < 8; i++) s += red[i];
            out[0] = s * (1.0f / (float)NB);
            g_ctr = 0;   // reset for next graph replay
        }
    }
}

// ---------------- launch -----------------------------------------------------
extern "C" void kernel_launch(void* const* d_in, const int* in_sizes, int n_in,
                              void* d_out, int out_size)
{
    const float* vi  = (const float*)d_in[0];
    const float* vo  = (const float*)d_in[1];
    const float* neg = (const float*)d_in[2];
    const float* Vm  = (const float*)d_in[3];
    const float* U   = (const float*)d_in[4];
    float* out = (float*)d_out;

    cudaFuncSetAttribute(gemm1_kernel, cudaFuncAttributeMaxDynamicSharedMemorySize, SMEM1);
    cudaFuncSetAttribute(gemm2_kernel, cudaFuncAttributeMaxDynamicSharedMemorySize, SMEM2);

    prep_kernel<<<5000, 256>>>(Vm, U);
    gemm1_kernel<<<dim3(8, NSPLIT), 256, SMEM1>>>(vi);
    reduce_kernel<<<128, 256>>>();
    gemm2_kernel<<<dim3(8, 250), 256, SMEM2>>>(vo, neg, out);
}